// round 15
// baseline (speedup 1.0000x reference)
#include <cuda_runtime.h>
#include <math.h>
#include <stdint.h>

#define Bn 64
#define Tn 512
#define Dn 256
#define Un 256
#define NCOL 64            // output columns owned by each CTA (Un / cluster4)

// (b*T + t, [r|z|h], u) : x@W + bias, precomputed
__device__ float g_xw[(size_t)Bn * Tn * 3 * Un];
// (cluster, t, u, ch) : masked state buffer, 2 chains packed
__device__ float g_buf[(size_t)(Bn / 2) * Tn * Un * 2];

__device__ __forceinline__ float sigmoidf_(float x) {
    return 1.f / (1.f + __expf(-x));
}
__device__ __forceinline__ uint32_t smem_u32(const void* p) {
    return (uint32_t)__cvta_generic_to_shared(p);
}
__device__ __forceinline__ void cluster_sync_() {
    asm volatile("barrier.cluster.arrive.aligned;" ::: "memory");
    asm volatile("barrier.cluster.wait.aligned;"   ::: "memory");
}
__device__ __forceinline__ void mbar_init(uint32_t bar, uint32_t cnt) {
    asm volatile("mbarrier.init.shared.b64 [%0], %1;" :: "r"(bar), "r"(cnt) : "memory");
}
__device__ __forceinline__ void mbar_expect_tx(uint32_t bar, uint32_t bytes) {
    asm volatile("mbarrier.arrive.expect_tx.shared.b64 _, [%0], %1;"
                 :: "r"(bar), "r"(bytes) : "memory");
}
__device__ __forceinline__ void mbar_wait(uint32_t bar, uint32_t parity) {
    asm volatile(
        "{\n\t.reg .pred P;\n\t"
        "W_%=:\n\t"
        "mbarrier.try_wait.parity.acquire.cta.shared::cta.b64 P, [%0], %1, 0x989680;\n\t"
        "@!P bra W_%=;\n\t"
        "}" :: "r"(bar), "r"(parity) : "memory");
}
typedef unsigned long long u64;
// async store of one f32 to cluster CTA `rank`'s smem, completing on its mbarrier
__device__ __forceinline__ void st_async_f32(uint32_t daddr, uint32_t baddr,
                                             int rank, float v) {
    uint32_t ra, rb;
    asm("mapa.shared::cluster.u32 %0, %1, %2;" : "=r"(ra) : "r"(daddr), "r"(rank));
    asm("mapa.shared::cluster.u32 %0, %1, %2;" : "=r"(rb) : "r"(baddr), "r"(rank));
    asm volatile(
        "st.async.shared::cluster.mbarrier::complete_tx::bytes.b32 [%0], %1, [%2];"
        :: "r"(ra), "r"(__float_as_uint(v)), "r"(rb) : "memory");
}
// async store of one u64
__device__ __forceinline__ void st_async_u64(uint32_t daddr, uint32_t baddr,
                                             int rank, u64 v) {
    uint32_t ra, rb;
    asm("mapa.shared::cluster.u32 %0, %1, %2;" : "=r"(ra) : "r"(daddr), "r"(rank));
    asm("mapa.shared::cluster.u32 %0, %1, %2;" : "=r"(rb) : "r"(baddr), "r"(rank));
    asm volatile(
        "st.async.shared::cluster.mbarrier::complete_tx::bytes.b64 [%0], %1, [%2];"
        :: "r"(ra), "l"(v), "r"(rb) : "memory");
}

// ---- packed f32x2 helpers ----
__device__ __forceinline__ u64 pack2(float a) {
    u64 r; asm("mov.b64 %0, {%1, %1};" : "=l"(r) : "f"(a)); return r;
}
__device__ __forceinline__ u64 ffma2(u64 a, u64 b, u64 c) {
    u64 d; asm("fma.rn.f32x2 %0, %1, %2, %3;" : "=l"(d) : "l"(a), "l"(b), "l"(c));
    return d;
}
__device__ __forceinline__ u64 fadd2(u64 a, u64 b) {
    u64 d; asm("add.rn.f32x2 %0, %1, %2;" : "=l"(d) : "l"(a), "l"(b));
    return d;
}
__device__ __forceinline__ float2 u2f(u64 v) {
    float2 r; asm("mov.b64 {%0, %1}, %2;" : "=f"(r.x), "=f"(r.y) : "l"(v));
    return r;
}

// ---------------------------------------------------------------------------
// Kernel 1: P = X @ [Wr | Wz | Wh] + biases. f32x2, double-buffered,
// As stored pre-duplicated as {a,a} u64 pairs (no pack movs in inner loop).
// ---------------------------------------------------------------------------
__global__ __launch_bounds__(256) void xw_gemm(
    const float* __restrict__ X,
    const float* __restrict__ Wr, const float* __restrict__ Wz,
    const float* __restrict__ Wh,
    const float* __restrict__ br, const float* __restrict__ bz,
    const float* __restrict__ bh)
{
    __shared__ u64   As[2][8][128];     // duplicated pairs
    __shared__ float Bs[2][8][128];
    const int tid = threadIdx.x;
    const int m0 = blockIdx.x * 128;
    const int n0 = blockIdx.y * 128;
    const int gi = n0 >> 8;
    const int u0 = n0 & 255;
    const float* __restrict__ W  = (gi == 0) ? Wr : (gi == 1 ? Wz : Wh);
    const float* __restrict__ bb = (gi == 0) ? br : (gi == 1 ? bz : bh);

    const int arow = tid >> 1;
    const int acol = (tid & 1) * 4;
    const int brow = tid >> 5;
    const int bcol = (tid & 31) * 4;
    const int ty = tid >> 4, tx = tid & 15;

    u64 acc[8][4];
#pragma unroll
    for (int i = 0; i < 8; i++)
#pragma unroll
        for (int j = 0; j < 4; j++) acc[i][j] = 0ull;

    {
        float4 a4 = *reinterpret_cast<const float4*>(
            &X[(size_t)(m0 + arow) * Dn + acol]);
        float4 b4 = *reinterpret_cast<const float4*>(
            &W[(size_t)brow * Un + u0 + bcol]);
        As[0][acol + 0][arow] = pack2(a4.x);
        As[0][acol + 1][arow] = pack2(a4.y);
        As[0][acol + 2][arow] = pack2(a4.z);
        As[0][acol + 3][arow] = pack2(a4.w);
        *reinterpret_cast<float4*>(&Bs[0][brow][bcol]) = b4;
    }
    __syncthreads();

    int buf = 0;
    for (int k0 = 0; k0 < Dn; k0 += 8) {
        const bool more = (k0 + 8 < Dn);
        float4 a4n, b4n;
        if (more) {
            a4n = *reinterpret_cast<const float4*>(
                &X[(size_t)(m0 + arow) * Dn + k0 + 8 + acol]);
            b4n = *reinterpret_cast<const float4*>(
                &W[(size_t)(k0 + 8 + brow) * Un + u0 + bcol]);
        }
#pragma unroll
        for (int k = 0; k < 8; k++) {
            const u64* ap = &As[buf][k][ty * 8];
            const u64* bp = reinterpret_cast<const u64*>(&Bs[buf][k][tx * 8]);
            const u64 b0 = bp[0], b1 = bp[1], b2 = bp[2], b3 = bp[3];
#pragma unroll
            for (int i = 0; i < 8; i++) {
                const u64 pa = ap[i];
                acc[i][0] = ffma2(pa, b0, acc[i][0]);
                acc[i][1] = ffma2(pa, b1, acc[i][1]);
                acc[i][2] = ffma2(pa, b2, acc[i][2]);
                acc[i][3] = ffma2(pa, b3, acc[i][3]);
            }
        }
        if (more) {
            As[buf ^ 1][acol + 0][arow] = pack2(a4n.x);
            As[buf ^ 1][acol + 1][arow] = pack2(a4n.y);
            As[buf ^ 1][acol + 2][arow] = pack2(a4n.z);
            As[buf ^ 1][acol + 3][arow] = pack2(a4n.w);
            *reinterpret_cast<float4*>(&Bs[buf ^ 1][brow][bcol]) = b4n;
        }
        __syncthreads();
        buf ^= 1;
    }
    const u64* bbp = reinterpret_cast<const u64*>(&bb[u0 + tx * 8]);
    const u64 bias2[4] = {bbp[0], bbp[1], bbp[2], bbp[3]};
#pragma unroll
    for (int i = 0; i < 8; i++) {
        u64* orow = reinterpret_cast<u64*>(
            g_xw + (size_t)(m0 + ty * 8 + i) * 768 + n0 + tx * 8);
#pragma unroll
        for (int j = 0; j < 4; j++)
            orow[j] = fadd2(acc[i][j], bias2[j]);
    }
}

// ---------------------------------------------------------------------------
// Kernel 2: recurrence with ROW-PARTITIONED phase 2 (no rs broadcast).
// CTA r's gate computes rs for its own 64 cols -> local smem; phase2-partial
// C_r[j] = sum_{i in own rows} rs_i * Uh[i][j] for ALL 256 j, then one
// st.async.b64 per thread scatters the 64-col slices to their owner CTAs.
// Ur register-resident; Uz SMEM; Uh stored [64 own rows][256 cols].
//
// smem (floats):
//   Uz   [256][64]        @0       65536 B
//   Uh   [64][256]        @16384   65536 B
//   part [8][4][2][64]    @32768   16384 B  (r partials)
//   zp   [8][2][64]       @36864    4096 B  (z partials)
//   sv   [4][256][2]      @37888    8192 B
//   hs3  [256][2]         @39936    2048 B
//   hsF  [256][2]         @40448    2048 B
//   rsl  [64][2]          @40960     512 B  (local rs)
//   Cbuf [4][64][2]       @41088    2048 B  (h partial slices, by src rank)
//   bars (2 x u64)        @41600      16 B
// ---------------------------------------------------------------------------
#define OFF_UH   16384
#define OFF_PART 32768
#define OFF_ZP   36864
#define OFF_S    37888
#define OFF_HS   39936
#define OFF_HSF  40448
#define OFF_RSL  40960
#define OFF_C    41088
#define OFF_BAR  41600
#define SMEM_BYTES (41604 * 4)

__global__ __launch_bounds__(256, 1) __cluster_dims__(4, 1, 1)
void rnn_seq4(const int*   __restrict__ deps,    // (T, 3)
              const int*   __restrict__ mask,    // (B, T)
              const float* __restrict__ init,    // (4, B, U)
              const float* __restrict__ Uzm, const float* __restrict__ Urm,
              const float* __restrict__ Uhm,
              float*       __restrict__ out)
{
    extern __shared__ float sm[];
    float* Uzs  = sm;
    float* Uhs  = sm + OFF_UH;
    float* part = sm + OFF_PART;
    float* zp   = sm + OFF_ZP;
    float* sv   = sm + OFF_S;
    float* hs3  = sm + OFF_HS;
    float* hsF  = sm + OFF_HSF;
    float* rsl  = sm + OFF_RSL;
    float* Cbuf = sm + OFF_C;

    const int tid  = threadIdx.x;
    const int rank = blockIdx.x & 3;
    const int cl   = blockIdx.x >> 2;
    const int b0   = cl * 2, b1 = b0 + 1;
    const int col0 = rank * NCOL;

    const uint32_t c_bar  = smem_u32(sm + OFF_BAR);
    const uint32_t st_bar = c_bar + 8;

    const int sl = tid >> 4;          // i-slice 0..15
    const int j0 = (tid & 15) * 4;    // 4 local columns

    // ---- Uz [256 rows][64 own cols]; Uh [64 own rows][256 cols] ----
    for (int idx = tid; idx < 256 * NCOL; idx += 256) {
        int i = idx >> 6, j = idx & 63;
        Uzs[idx] = Uzm[i * Un + col0 + j];
        int hi = idx >> 8, hj = idx & 255;
        Uhs[idx] = Uhm[(col0 + hi) * Un + hj];
    }
    // Ur slice into registers
    float4 wr4[16];
#pragma unroll
    for (int rr = 0; rr < 16; rr++)
        wr4[rr] = *reinterpret_cast<const float4*>(
            &Urm[((sl << 4) + rr) * Un + col0 + j0]);
    if (tid == 0) { mbar_init(c_bar, 1); mbar_init(st_bar, 1); }

    // ---- preload initial states (t=0) ----
#pragma unroll
    for (int k = 0; k < 4; k++) {
        sv[(k * 256 + tid) * 2 + 0] = init[((size_t)k * Bn + b0) * Un + tid];
        sv[(k * 256 + tid) * 2 + 1] = init[((size_t)k * Bn + b1) * Un + tid];
    }
    // ---- preload xw/mask for t=0 (gate threads only) ----
    float xwr = 0.f, xwz = 0.f, xwh = 0.f;
    int   mreg = 0;
    const int ch = tid >> 6, jg = tid & 63;        // valid for tid<128
    const int bbg = ch ? b1 : b0;
    if (tid < 128) {
        const float* base = g_xw + ((size_t)bbg * Tn + 0) * 768;
        xwr = base[col0 + jg];
        xwz = base[256 + col0 + jg];
        xwh = base[512 + col0 + jg];
        mreg = mask[bbg * Tn + 0];
    }
    asm volatile("fence.proxy.async.shared::cta;" ::: "memory");
    __syncthreads();
    cluster_sync_();          // bars visible cluster-wide before any st.async

    u64  pf[3]  = {0ull, 0ull, 0ull};
    bool def[3] = {false, false, false};

    for (int t = 0; t < Tn; t++) {
        if (tid == 0) mbar_expect_tx(c_bar, 2048);

        // ---- top: sv[1..3] update + hs3 from registers ----
        u64 p0, p1, p2;
        if (t == 0) {
            p0 = *reinterpret_cast<const u64*>(&sv[(1*256 + tid) * 2]);
            p1 = *reinterpret_cast<const u64*>(&sv[(2*256 + tid) * 2]);
            p2 = *reinterpret_cast<const u64*>(&sv[(3*256 + tid) * 2]);
        } else {
            p0 = def[0] ? 0ull : pf[0];
            p1 = def[1] ? 0ull : pf[1];
            p2 = def[2] ? 0ull : pf[2];
            *reinterpret_cast<u64*>(&sv[(1*256 + tid) * 2]) = p0;
            *reinterpret_cast<u64*>(&sv[(2*256 + tid) * 2]) = p1;
            *reinterpret_cast<u64*>(&sv[(3*256 + tid) * 2]) = p2;
        }
        *reinterpret_cast<u64*>(&hs3[tid * 2]) = fadd2(fadd2(p0, p1), p2);
        const int cnt = (int)def[0] + (int)def[1] + (int)def[2];
        const float cnt1f = 1.f + (float)cnt;
        __syncthreads();

        // ---- xw/mask prefetch for t+1 (pre-wait zone) ----
        float nxr = 0.f, nxz = 0.f, nxh = 0.f;
        int nm = 0;
        if (tid < 128) {
            const int tn = (t + 1 < Tn) ? t + 1 : t;
            const float* base = g_xw + ((size_t)bbg * Tn + tn) * 768;
            nxr = base[col0 + jg];
            nxz = base[256 + col0 + jg];
            nxh = base[512 + col0 + jg];
            nm  = mask[bbg * Tn + tn];
        }

        // ---- phase 1a: r preacts for states 1..3 (pre-wait, regs Ur) ----
        u64 aR[4][4];
#pragma unroll
        for (int k = 0; k < 4; k++)
#pragma unroll
            for (int c = 0; c < 4; c++) aR[k][c] = 0ull;
#pragma unroll
        for (int rr = 0; rr < 16; rr++) {
            const int i = (sl << 4) + rr;
            const u64 s1 = *reinterpret_cast<const u64*>(&sv[(1*256 + i) * 2]);
            const u64 s2 = *reinterpret_cast<const u64*>(&sv[(2*256 + i) * 2]);
            const u64 s3 = *reinterpret_cast<const u64*>(&sv[(3*256 + i) * 2]);
            const u64 w0 = pack2(wr4[rr].x), w1 = pack2(wr4[rr].y),
                      w2 = pack2(wr4[rr].z), w3 = pack2(wr4[rr].w);
            aR[1][0] = ffma2(w0, s1, aR[1][0]);
            aR[1][1] = ffma2(w1, s1, aR[1][1]);
            aR[1][2] = ffma2(w2, s1, aR[1][2]);
            aR[1][3] = ffma2(w3, s1, aR[1][3]);
            aR[2][0] = ffma2(w0, s2, aR[2][0]);
            aR[2][1] = ffma2(w1, s2, aR[2][1]);
            aR[2][2] = ffma2(w2, s2, aR[2][2]);
            aR[2][3] = ffma2(w3, s2, aR[2][3]);
            aR[3][0] = ffma2(w0, s3, aR[3][0]);
            aR[3][1] = ffma2(w1, s3, aR[3][1]);
            aR[3][2] = ffma2(w2, s3, aR[3][2]);
            aR[3][3] = ffma2(w3, s3, aR[3][3]);
        }

        // ---- wait for s0 = st(t-1); then set st expectation ----
        if (t > 0) mbar_wait(st_bar, (t - 1) & 1);
        if (tid == 0) mbar_expect_tx(st_bar, 2048);

        // ---- g_buf row t-1 + data prefetch for t+1 ----
        const u64 s0mine = *reinterpret_cast<const u64*>(&sv[tid * 2]);
        if (t > 0)
            *reinterpret_cast<u64*>(
                &g_buf[(((size_t)cl * Tn + (t - 1)) * Un + tid) * 2]) = s0mine;
        u64  pfN[3];
        bool defN[3];
#pragma unroll
        for (int k = 0; k < 3; k++) {
            const int d = deps[t * 3 + k];
            defN[k] = (d >= t);
            pfN[k] = 0ull;
            if (d < t)
                pfN[k] = *reinterpret_cast<const u64*>(
                    &g_buf[(((size_t)cl * Tn + d) * Un + tid) * 2]);
        }

        // ---- phase 1b: s0 dot (regs Ur) + hsF snapshot ----
        const u64 cf = pack2(cnt1f);
        u64 cc[4] = {0ull, 0ull, 0ull, 0ull};
#pragma unroll
        for (int rr = 0; rr < 16; rr++) {
            const int i = (sl << 4) + rr;
            const u64 s0 = *reinterpret_cast<const u64*>(&sv[(0*256 + i) * 2]);
            const u64 h3 = *reinterpret_cast<const u64*>(&hs3[i * 2]);
            *reinterpret_cast<u64*>(&hsF[i * 2]) = ffma2(cf, s0, h3);
            cc[0] = ffma2(pack2(wr4[rr].x), s0, cc[0]);
            cc[1] = ffma2(pack2(wr4[rr].y), s0, cc[1]);
            cc[2] = ffma2(pack2(wr4[rr].z), s0, cc[2]);
            cc[3] = ffma2(pack2(wr4[rr].w), s0, cc[3]);
        }
#pragma unroll
        for (int c = 0; c < 4; c++) {
            aR[0][c] = fadd2(aR[0][c], cc[c]);
            if (def[0]) aR[1][c] = fadd2(aR[1][c], cc[c]);
            if (def[1]) aR[2][c] = fadd2(aR[2][c], cc[c]);
            if (def[2]) aR[3][c] = fadd2(aR[3][c], cc[c]);
        }
#pragma unroll
        for (int k = 0; k < 4; k++)
#pragma unroll
            for (int c = 0; c < 4; c++)
                aR[k][c] = fadd2(aR[k][c],
                    __shfl_xor_sync(0xffffffffu, aR[k][c], 16));
        if (!(sl & 1)) {
            const int p = sl >> 1;
#pragma unroll
            for (int g = 0; g < 4; g++) {
                float2 a0 = u2f(aR[g][0]), a1 = u2f(aR[g][1]);
                float2 a2 = u2f(aR[g][2]), a3 = u2f(aR[g][3]);
                *reinterpret_cast<float4*>(&part[((p*4+g)*2 + 0) * 64 + j0]) =
                    make_float4(a0.x, a1.x, a2.x, a3.x);
                *reinterpret_cast<float4*>(&part[((p*4+g)*2 + 1) * 64 + j0]) =
                    make_float4(a0.y, a1.y, a2.y, a3.y);
            }
        }
        __syncthreads();

        // ---- gate stage (tid<128): r gates, rsum -> LOCAL rsl ----
        float hsumc = 0.f, prevc = 0.f;
        if (tid < 128) {
            float pr[4] = {0.f, 0.f, 0.f, 0.f};
#pragma unroll
            for (int p = 0; p < 8; p++)
#pragma unroll
                for (int g = 0; g < 4; g++)
                    pr[g] += part[((p*4+g)*2 + ch) * 64 + jg];
            const int col = col0 + jg;
            const float s0c = sv[(0*256 + col) * 2 + ch];
            const float s1v = sv[(1*256 + col) * 2 + ch];
            const float s2v = sv[(2*256 + col) * 2 + ch];
            const float s3v = sv[(3*256 + col) * 2 + ch];
            const float s1g = def[0] ? s0c : s1v;
            const float s2g = def[1] ? s0c : s2v;
            const float s3g = def[2] ? s0c : s3v;
            hsumc = s0c * cnt1f + s1v + s2v + s3v;
            prevc = (t == 0) ? 0.f : s0c;
            const float rsum = sigmoidf_(xwr + pr[0]) * s0c
                             + sigmoidf_(xwr + pr[1]) * s1g
                             + sigmoidf_(xwr + pr[2]) * s2g
                             + sigmoidf_(xwr + pr[3]) * s3g;
            rsl[jg * 2 + ch] = rsum;              // local store only
        }
        __syncthreads();                           // rsl visible CTA-wide

        // ---- phase 2 partial: C[j] = sum_{i in own rows} rs_i*Uh[i][j],
        //      thread handles global column j = tid; one st.async.b64 push ----
        {
            u64 C = 0ull;
#pragma unroll 8
            for (int i = 0; i < 64; i++) {
                const u64 rp = *reinterpret_cast<const u64*>(&rsl[i * 2]);
                C = ffma2(pack2(Uhs[(i << 8) + tid]), rp, C);
            }
            const int dst = tid >> 6;              // owner CTA of col tid
            const int jl  = tid & 63;
            const uint32_t da = smem_u32(&Cbuf[((rank << 6) + jl) * 2]);
            st_async_u64(da, c_bar, dst, C);
        }

        // ---- Z matvec (all threads; Uz smem, hsF smem) — hides C delivery ----
        u64 aZ[4];
#pragma unroll
        for (int c = 0; c < 4; c++) aZ[c] = 0ull;
#pragma unroll
        for (int rr = 0; rr < 16; rr++) {
            const int i = (sl << 4) + rr;
            const float4 wz = *reinterpret_cast<const float4*>(&Uzs[(i << 6) + j0]);
            const u64 hp = *reinterpret_cast<const u64*>(&hsF[i * 2]);
            aZ[0] = ffma2(pack2(wz.x), hp, aZ[0]);
            aZ[1] = ffma2(pack2(wz.y), hp, aZ[1]);
            aZ[2] = ffma2(pack2(wz.z), hp, aZ[2]);
            aZ[3] = ffma2(pack2(wz.w), hp, aZ[3]);
        }
#pragma unroll
        for (int c = 0; c < 4; c++)
            aZ[c] = fadd2(aZ[c],
                __shfl_xor_sync(0xffffffffu, aZ[c], 16));
        if (!(sl & 1)) {
            const int p = sl >> 1;
            float2 c0 = u2f(aZ[0]), c1 = u2f(aZ[1]);
            float2 c2 = u2f(aZ[2]), c3 = u2f(aZ[3]);
            *reinterpret_cast<float4*>(&zp[(p*2 + 0) * 64 + j0]) =
                make_float4(c0.x, c1.x, c2.x, c3.x);
            *reinterpret_cast<float4*>(&zp[(p*2 + 1) * 64 + j0]) =
                make_float4(c0.y, c1.y, c2.y, c3.y);
        }
        __syncthreads();                           // zp visible
        mbar_wait(c_bar, t & 1);                   // all 4 C slices landed

        // ---- final: z, h, mask, outputs, push new state ----
        if (tid < 128) {
            const int col = col0 + jg;
            float2 phc = make_float2(0.f, 0.f);
#pragma unroll
            for (int s = 0; s < 4; s++) {
                float2 cv = u2f(*reinterpret_cast<const u64*>(
                    &Cbuf[((s << 6) + jg) * 2]));
                phc.x += cv.x; phc.y += cv.y;
            }
            const float ph = ch ? phc.y : phc.x;
            float pz = 0.f;
#pragma unroll
            for (int p = 0; p < 8; p++) pz += zp[(p*2 + ch) * 64 + jg];
            const float z  = sigmoidf_(xwz + pz);
            const float ht = 2.f * sigmoidf_(2.f * (xwh + ph)) - 1.f;  // tanh
            const float h  = z * hsumc * 0.25f + (1.f - z) * ht;
            const float st = mreg ? h : prevc;
            const uint32_t da = smem_u32(&sv[(0 * 256 + col) * 2 + ch]);
#pragma unroll
            for (int r4 = 0; r4 < 4; r4++) st_async_f32(da, st_bar, r4, st);
            const float ov = mreg ? h : 0.f;
            out[((size_t)bbg * Tn + t) * Un + col] = ov;
            if (t == Tn - 1) {
                out[(size_t)Bn * Tn * Un + (size_t)bbg * Un + col] = ov;
                out[(size_t)Bn * Tn * Un + (size_t)Bn * Un + (size_t)bbg * Un + col] = st;
            }
        }

        // ---- rotate pipeline registers ----
#pragma unroll
        for (int k = 0; k < 3; k++) { pf[k] = pfN[k]; def[k] = defN[k]; }
        xwr = nxr; xwz = nxz; xwh = nxh; mreg = nm;
    }

    // ---- exit drain: all inbound st.async must land before any CTA exits ----
    mbar_wait(st_bar, (Tn - 1) & 1);
    cluster_sync_();
}

// ---------------------------------------------------------------------------
// Inputs: 0 inputs, 1 dependencies, 2 mask, 3 initial_states,
// 4 Wz, 5 Wr, 6 Wh, 7 Uz, 8 Ur, 9 Uh, 10 bz, 11 br, 12 bh
// ---------------------------------------------------------------------------
extern "C" void kernel_launch(void* const* d_in, const int* in_sizes, int n_in,
                              void* d_out, int out_size) {
    const float* X    = (const float*)d_in[0];
    const int*   deps = (const int*)  d_in[1];
    const int*   mask = (const int*)  d_in[2];
    const float* init = (const float*)d_in[3];
    const float* Wz   = (const float*)d_in[4];
    const float* Wr   = (const float*)d_in[5];
    const float* Wh   = (const float*)d_in[6];
    const float* Uz   = (const float*)d_in[7];
    const float* Ur   = (const float*)d_in[8];
    const float* Uh   = (const float*)d_in[9];
    const float* bz   = (const float*)d_in[10];
    const float* br   = (const float*)d_in[11];
    const float* bh   = (const float*)d_in[12];
    float* out = (float*)d_out;

    cudaFuncSetAttribute(rnn_seq4, cudaFuncAttributeMaxDynamicSharedMemorySize,
                         SMEM_BYTES);

    dim3 g1(256, 6);   // (32768/128, 768/128)
    xw_gemm<<<g1, 256>>>(X, Wr, Wz, Wh, br, bz, bh);
    rnn_seq4<<<128, 256, SMEM_BYTES>>>(deps, mask, init, Uz, Ur, Uh, out);
}

// round 16
// speedup vs baseline: 1.0863x; 1.0863x over previous
#include <cuda_runtime.h>
#include <math.h>
#include <stdint.h>

#define Bn 64
#define Tn 512
#define Dn 256
#define Un 256
#define NCOL 64            // output columns owned by each CTA (Un / cluster4)

// (b*T + t, [r|z|h], u) : x@W + bias, precomputed
__device__ float g_xw[(size_t)Bn * Tn * 3 * Un];
// (cluster, t, u, ch) : masked state buffer, 2 chains packed
__device__ float g_buf[(size_t)(Bn / 2) * Tn * Un * 2];

__device__ __forceinline__ float sigmoidf_(float x) {
    return 1.f / (1.f + __expf(-x));
}
__device__ __forceinline__ uint32_t smem_u32(const void* p) {
    return (uint32_t)__cvta_generic_to_shared(p);
}
__device__ __forceinline__ void cluster_sync_() {
    asm volatile("barrier.cluster.arrive.aligned;" ::: "memory");
    asm volatile("barrier.cluster.wait.aligned;"   ::: "memory");
}
__device__ __forceinline__ void mbar_init(uint32_t bar, uint32_t cnt) {
    asm volatile("mbarrier.init.shared.b64 [%0], %1;" :: "r"(bar), "r"(cnt) : "memory");
}
__device__ __forceinline__ void mbar_expect_tx(uint32_t bar, uint32_t bytes) {
    asm volatile("mbarrier.arrive.expect_tx.shared.b64 _, [%0], %1;"
                 :: "r"(bar), "r"(bytes) : "memory");
}
__device__ __forceinline__ void mbar_wait(uint32_t bar, uint32_t parity) {
    asm volatile(
        "{\n\t.reg .pred P;\n\t"
        "W_%=:\n\t"
        "mbarrier.try_wait.parity.acquire.cta.shared::cta.b64 P, [%0], %1, 0x989680;\n\t"
        "@!P bra W_%=;\n\t"
        "}" :: "r"(bar), "r"(parity) : "memory");
}
// async store of one f32 to cluster CTA `rank`'s smem, completing on its mbarrier
__device__ __forceinline__ void st_async_f32(uint32_t daddr, uint32_t baddr,
                                             int rank, float v) {
    uint32_t ra, rb;
    asm("mapa.shared::cluster.u32 %0, %1, %2;" : "=r"(ra) : "r"(daddr), "r"(rank));
    asm("mapa.shared::cluster.u32 %0, %1, %2;" : "=r"(rb) : "r"(baddr), "r"(rank));
    asm volatile(
        "st.async.shared::cluster.mbarrier::complete_tx::bytes.b32 [%0], %1, [%2];"
        :: "r"(ra), "r"(__float_as_uint(v)), "r"(rb) : "memory");
}

// ---- packed f32x2 helpers ----
typedef unsigned long long u64;
__device__ __forceinline__ u64 pack2(float a) {
    u64 r; asm("mov.b64 %0, {%1, %1};" : "=l"(r) : "f"(a)); return r;
}
__device__ __forceinline__ u64 ffma2(u64 a, u64 b, u64 c) {
    u64 d; asm("fma.rn.f32x2 %0, %1, %2, %3;" : "=l"(d) : "l"(a), "l"(b), "l"(c));
    return d;
}
__device__ __forceinline__ u64 fadd2(u64 a, u64 b) {
    u64 d; asm("add.rn.f32x2 %0, %1, %2;" : "=l"(d) : "l"(a), "l"(b));
    return d;
}
__device__ __forceinline__ float2 u2f(u64 v) {
    float2 r; asm("mov.b64 {%0, %1}, %2;" : "=f"(r.x), "=f"(r.y) : "l"(v));
    return r;
}

// ---------------------------------------------------------------------------
// Kernel 1: P = X @ [Wr | Wz | Wh] + biases. f32x2, double-buffered,
// As stored pre-duplicated as {a,a} u64 pairs (no pack movs in inner loop).
// ---------------------------------------------------------------------------
__global__ __launch_bounds__(256) void xw_gemm(
    const float* __restrict__ X,
    const float* __restrict__ Wr, const float* __restrict__ Wz,
    const float* __restrict__ Wh,
    const float* __restrict__ br, const float* __restrict__ bz,
    const float* __restrict__ bh)
{
    __shared__ u64   As[2][8][128];     // duplicated pairs
    __shared__ float Bs[2][8][128];
    const int tid = threadIdx.x;
    const int m0 = blockIdx.x * 128;
    const int n0 = blockIdx.y * 128;
    const int gi = n0 >> 8;
    const int u0 = n0 & 255;
    const float* __restrict__ W  = (gi == 0) ? Wr : (gi == 1 ? Wz : Wh);
    const float* __restrict__ bb = (gi == 0) ? br : (gi == 1 ? bz : bh);

    const int arow = tid >> 1;
    const int acol = (tid & 1) * 4;
    const int brow = tid >> 5;
    const int bcol = (tid & 31) * 4;
    const int ty = tid >> 4, tx = tid & 15;

    u64 acc[8][4];
#pragma unroll
    for (int i = 0; i < 8; i++)
#pragma unroll
        for (int j = 0; j < 4; j++) acc[i][j] = 0ull;

    {
        float4 a4 = *reinterpret_cast<const float4*>(
            &X[(size_t)(m0 + arow) * Dn + acol]);
        float4 b4 = *reinterpret_cast<const float4*>(
            &W[(size_t)brow * Un + u0 + bcol]);
        As[0][acol + 0][arow] = pack2(a4.x);
        As[0][acol + 1][arow] = pack2(a4.y);
        As[0][acol + 2][arow] = pack2(a4.z);
        As[0][acol + 3][arow] = pack2(a4.w);
        *reinterpret_cast<float4*>(&Bs[0][brow][bcol]) = b4;
    }
    __syncthreads();

    int buf = 0;
    for (int k0 = 0; k0 < Dn; k0 += 8) {
        const bool more = (k0 + 8 < Dn);
        float4 a4n, b4n;
        if (more) {
            a4n = *reinterpret_cast<const float4*>(
                &X[(size_t)(m0 + arow) * Dn + k0 + 8 + acol]);
            b4n = *reinterpret_cast<const float4*>(
                &W[(size_t)(k0 + 8 + brow) * Un + u0 + bcol]);
        }
#pragma unroll
        for (int k = 0; k < 8; k++) {
            const u64* ap = &As[buf][k][ty * 8];
            const u64* bp = reinterpret_cast<const u64*>(&Bs[buf][k][tx * 8]);
            const u64 b0 = bp[0], b1 = bp[1], b2 = bp[2], b3 = bp[3];
#pragma unroll
            for (int i = 0; i < 8; i++) {
                const u64 pa = ap[i];
                acc[i][0] = ffma2(pa, b0, acc[i][0]);
                acc[i][1] = ffma2(pa, b1, acc[i][1]);
                acc[i][2] = ffma2(pa, b2, acc[i][2]);
                acc[i][3] = ffma2(pa, b3, acc[i][3]);
            }
        }
        if (more) {
            As[buf ^ 1][acol + 0][arow] = pack2(a4n.x);
            As[buf ^ 1][acol + 1][arow] = pack2(a4n.y);
            As[buf ^ 1][acol + 2][arow] = pack2(a4n.z);
            As[buf ^ 1][acol + 3][arow] = pack2(a4n.w);
            *reinterpret_cast<float4*>(&Bs[buf ^ 1][brow][bcol]) = b4n;
        }
        __syncthreads();
        buf ^= 1;
    }
    const u64* bbp = reinterpret_cast<const u64*>(&bb[u0 + tx * 8]);
    const u64 bias2[4] = {bbp[0], bbp[1], bbp[2], bbp[3]};
#pragma unroll
    for (int i = 0; i < 8; i++) {
        u64* orow = reinterpret_cast<u64*>(
            g_xw + (size_t)(m0 + ty * 8 + i) * 768 + n0 + tx * 8);
#pragma unroll
        for (int j = 0; j < 4; j++)
            orow[j] = fadd2(acc[i][j], bias2[j]);
    }
}

// ---------------------------------------------------------------------------
// Kernel 2: recurrence — exact R14 structure (best measured). Ur in
// registers (read twice per step: phase1a + phase1b), Uz/Uh in SMEM,
// column-partitioned phase 2 with rs broadcast, s0-pipelined step.
//
// smem (floats):
//   W    [2][256][64]     @0       131072 B  (Uz @0, Uh @16384)
//   part [8][5][2][64]    @32768    20480 B  (g0..3 = r; g4 = z; g0 reused h)
//   sv   [4][256][2]      @37888     8192 B
//   hs3  [256][2]         @39936     2048 B
//   hsF  [256][2]         @40448     2048 B
//   rs   [256][2]         @40960     2048 B
//   bars (2 x u64)        @41472       16 B
// ---------------------------------------------------------------------------
#define OFF_PART 32768
#define OFF_S    37888
#define OFF_HS   39936
#define OFF_HSF  40448
#define OFF_RS   40960
#define OFF_BAR  41472
#define SMEM_BYTES (41476 * 4)

__global__ __launch_bounds__(256, 1) __cluster_dims__(4, 1, 1)
void rnn_seq4(const int*   __restrict__ deps,    // (T, 3)
              const int*   __restrict__ mask,    // (B, T)
              const float* __restrict__ init,    // (4, B, U)
              const float* __restrict__ Uzm, const float* __restrict__ Urm,
              const float* __restrict__ Uhm,
              float*       __restrict__ out)
{
    extern __shared__ float sm[];
    float* Ws   = sm;
    float* part = sm + OFF_PART;
    float* sv   = sm + OFF_S;
    float* hs3  = sm + OFF_HS;
    float* hsF  = sm + OFF_HSF;
    float* rs   = sm + OFF_RS;

    const int tid  = threadIdx.x;
    const int rank = blockIdx.x & 3;
    const int cl   = blockIdx.x >> 2;
    const int b0   = cl * 2, b1 = b0 + 1;
    const int col0 = rank * NCOL;

    const uint32_t rs_bar = smem_u32(sm + OFF_BAR);
    const uint32_t st_bar = rs_bar + 8;

    const int sl = tid >> 4;          // i-slice 0..15
    const int j0 = (tid & 15) * 4;    // 4 local columns

    // ---- Uz/Uh into smem; Ur into registers (thread-private slice) ----
    for (int idx = tid; idx < 256 * NCOL; idx += 256) {
        int i = idx >> 6, j = idx & 63;
        Ws[idx]          = Uzm[i * Un + col0 + j];
        Ws[16384 + idx]  = Uhm[i * Un + col0 + j];
    }
    float4 wr4[16];
#pragma unroll
    for (int rr = 0; rr < 16; rr++)
        wr4[rr] = *reinterpret_cast<const float4*>(
            &Urm[((sl << 4) + rr) * Un + col0 + j0]);
    if (tid == 0) { mbar_init(rs_bar, 1); mbar_init(st_bar, 1); }

    // ---- preload initial states (t=0) ----
#pragma unroll
    for (int k = 0; k < 4; k++) {
        sv[(k * 256 + tid) * 2 + 0] = init[((size_t)k * Bn + b0) * Un + tid];
        sv[(k * 256 + tid) * 2 + 1] = init[((size_t)k * Bn + b1) * Un + tid];
    }
    // ---- preload xw/mask for t=0 (gate threads only) ----
    float xwr = 0.f, xwz = 0.f, xwh = 0.f;
    int   mreg = 0;
    const int ch = tid >> 6, jg = tid & 63;        // valid for tid<128
    const int bbg = ch ? b1 : b0;
    if (tid < 128) {
        const float* base = g_xw + ((size_t)bbg * Tn + 0) * 768;
        xwr = base[col0 + jg];
        xwz = base[256 + col0 + jg];
        xwh = base[512 + col0 + jg];
        mreg = mask[bbg * Tn + 0];
    }
    asm volatile("fence.proxy.async.shared::cta;" ::: "memory");
    __syncthreads();
    cluster_sync_();          // bars visible cluster-wide before any st.async

    u64  pf[3]  = {0ull, 0ull, 0ull};
    bool def[3] = {false, false, false};

    for (int t = 0; t < Tn; t++) {
        if (tid == 0) mbar_expect_tx(rs_bar, 2048);

        // ---- top: sv[1..3] update + hs3 from registers ----
        u64 p0, p1, p2;
        if (t == 0) {
            p0 = *reinterpret_cast<const u64*>(&sv[(1*256 + tid) * 2]);
            p1 = *reinterpret_cast<const u64*>(&sv[(2*256 + tid) * 2]);
            p2 = *reinterpret_cast<const u64*>(&sv[(3*256 + tid) * 2]);
        } else {
            p0 = def[0] ? 0ull : pf[0];
            p1 = def[1] ? 0ull : pf[1];
            p2 = def[2] ? 0ull : pf[2];
            *reinterpret_cast<u64*>(&sv[(1*256 + tid) * 2]) = p0;
            *reinterpret_cast<u64*>(&sv[(2*256 + tid) * 2]) = p1;
            *reinterpret_cast<u64*>(&sv[(3*256 + tid) * 2]) = p2;
        }
        *reinterpret_cast<u64*>(&hs3[tid * 2]) = fadd2(fadd2(p0, p1), p2);
        const int cnt = (int)def[0] + (int)def[1] + (int)def[2];
        const float cnt1f = 1.f + (float)cnt;
        __syncthreads();

        // ---- xw/mask prefetch for t+1 (pre-wait zone) ----
        float nxr = 0.f, nxz = 0.f, nxh = 0.f;
        int nm = 0;
        if (tid < 128) {
            const int tn = (t + 1 < Tn) ? t + 1 : t;
            const float* base = g_xw + ((size_t)bbg * Tn + tn) * 768;
            nxr = base[col0 + jg];
            nxz = base[256 + col0 + jg];
            nxh = base[512 + col0 + jg];
            nm  = mask[bbg * Tn + tn];
        }

        // ---- phase 1a: r preacts for states 1..3 (pre-wait, regs Ur) ----
        u64 aR[4][4];
#pragma unroll
        for (int k = 0; k < 4; k++)
#pragma unroll
            for (int c = 0; c < 4; c++) aR[k][c] = 0ull;
#pragma unroll
        for (int rr = 0; rr < 16; rr++) {
            const int i = (sl << 4) + rr;
            const u64 s1 = *reinterpret_cast<const u64*>(&sv[(1*256 + i) * 2]);
            const u64 s2 = *reinterpret_cast<const u64*>(&sv[(2*256 + i) * 2]);
            const u64 s3 = *reinterpret_cast<const u64*>(&sv[(3*256 + i) * 2]);
            const u64 w0 = pack2(wr4[rr].x), w1 = pack2(wr4[rr].y),
                      w2 = pack2(wr4[rr].z), w3 = pack2(wr4[rr].w);
            aR[1][0] = ffma2(w0, s1, aR[1][0]);
            aR[1][1] = ffma2(w1, s1, aR[1][1]);
            aR[1][2] = ffma2(w2, s1, aR[1][2]);
            aR[1][3] = ffma2(w3, s1, aR[1][3]);
            aR[2][0] = ffma2(w0, s2, aR[2][0]);
            aR[2][1] = ffma2(w1, s2, aR[2][1]);
            aR[2][2] = ffma2(w2, s2, aR[2][2]);
            aR[2][3] = ffma2(w3, s2, aR[2][3]);
            aR[3][0] = ffma2(w0, s3, aR[3][0]);
            aR[3][1] = ffma2(w1, s3, aR[3][1]);
            aR[3][2] = ffma2(w2, s3, aR[3][2]);
            aR[3][3] = ffma2(w3, s3, aR[3][3]);
        }

        // ---- wait for s0 = st(t-1); then set st expectation for this step ----
        if (t > 0) mbar_wait(st_bar, (t - 1) & 1);
        if (tid == 0) mbar_expect_tx(st_bar, 2048);

        // ---- g_buf row t-1 + data prefetch for t+1 ----
        const u64 s0mine = *reinterpret_cast<const u64*>(&sv[tid * 2]);
        if (t > 0)
            *reinterpret_cast<u64*>(
                &g_buf[(((size_t)cl * Tn + (t - 1)) * Un + tid) * 2]) = s0mine;
        u64  pfN[3];
        bool defN[3];
#pragma unroll
        for (int k = 0; k < 3; k++) {
            const int d = deps[t * 3 + k];
            defN[k] = (d >= t);      // d == t: gathered state is st(t) = next s0
            pfN[k] = 0ull;
            if (d < t)
                pfN[k] = *reinterpret_cast<const u64*>(
                    &g_buf[(((size_t)cl * Tn + d) * Un + tid) * 2]);
        }

        // ---- phase 1b: s0 dot (regs Ur) + hsF snapshot ----
        const u64 cf = pack2(cnt1f);
        u64 cc[4] = {0ull, 0ull, 0ull, 0ull};
#pragma unroll
        for (int rr = 0; rr < 16; rr++) {
            const int i = (sl << 4) + rr;
            const u64 s0 = *reinterpret_cast<const u64*>(&sv[(0*256 + i) * 2]);
            const u64 h3 = *reinterpret_cast<const u64*>(&hs3[i * 2]);
            *reinterpret_cast<u64*>(&hsF[i * 2]) = ffma2(cf, s0, h3);
            cc[0] = ffma2(pack2(wr4[rr].x), s0, cc[0]);
            cc[1] = ffma2(pack2(wr4[rr].y), s0, cc[1]);
            cc[2] = ffma2(pack2(wr4[rr].z), s0, cc[2]);
            cc[3] = ffma2(pack2(wr4[rr].w), s0, cc[3]);
        }
#pragma unroll
        for (int c = 0; c < 4; c++) {
            aR[0][c] = fadd2(aR[0][c], cc[c]);
            if (def[0]) aR[1][c] = fadd2(aR[1][c], cc[c]);
            if (def[1]) aR[2][c] = fadd2(aR[2][c], cc[c]);
            if (def[2]) aR[3][c] = fadd2(aR[3][c], cc[c]);
        }
#pragma unroll
        for (int k = 0; k < 4; k++)
#pragma unroll
            for (int c = 0; c < 4; c++)
                aR[k][c] = fadd2(aR[k][c],
                    __shfl_xor_sync(0xffffffffu, aR[k][c], 16));
        if (!(sl & 1)) {
            const int p = sl >> 1;
#pragma unroll
            for (int g = 0; g < 4; g++) {
                float2 a0 = u2f(aR[g][0]), a1 = u2f(aR[g][1]);
                float2 a2 = u2f(aR[g][2]), a3 = u2f(aR[g][3]);
                *reinterpret_cast<float4*>(&part[((p*5+g)*2 + 0) * 64 + j0]) =
                    make_float4(a0.x, a1.x, a2.x, a3.x);
                *reinterpret_cast<float4*>(&part[((p*5+g)*2 + 1) * 64 + j0]) =
                    make_float4(a0.y, a1.y, a2.y, a3.y);
            }
        }
        __syncthreads();

        // ---- gate stage (tid<128): r gates, rsum; snapshots; push rs ----
        float hsumc = 0.f, prevc = 0.f;
        if (tid < 128) {
            float pr[4] = {0.f, 0.f, 0.f, 0.f};
#pragma unroll
            for (int p = 0; p < 8; p++)
#pragma unroll
                for (int g = 0; g < 4; g++)
                    pr[g] += part[((p*5+g)*2 + ch) * 64 + jg];
            const int col = col0 + jg;
            const float s0c = sv[(0*256 + col) * 2 + ch];
            const float s1v = sv[(1*256 + col) * 2 + ch];   // 0 if deferred
            const float s2v = sv[(2*256 + col) * 2 + ch];
            const float s3v = sv[(3*256 + col) * 2 + ch];
            const float s1g = def[0] ? s0c : s1v;
            const float s2g = def[1] ? s0c : s2v;
            const float s3g = def[2] ? s0c : s3v;
            hsumc = s0c * cnt1f + s1v + s2v + s3v;
            prevc = (t == 0) ? 0.f : s0c;
            const float rsum = sigmoidf_(xwr + pr[0]) * s0c
                             + sigmoidf_(xwr + pr[1]) * s1g
                             + sigmoidf_(xwr + pr[2]) * s2g
                             + sigmoidf_(xwr + pr[3]) * s3g;
            const uint32_t da = smem_u32(&rs[col * 2 + ch]);
#pragma unroll
            for (int r4 = 0; r4 < 4; r4++) st_async_f32(da, rs_bar, r4, rsum);
        }

        // ---- Z matvec (all threads; Uz in smem, hsF in smem) ----
        u64 aZ[4];
#pragma unroll
        for (int c = 0; c < 4; c++) aZ[c] = 0ull;
#pragma unroll
        for (int rr = 0; rr < 16; rr++) {
            const int i = (sl << 4) + rr;
            const float4 wz = *reinterpret_cast<const float4*>(&Ws[(i << 6) + j0]);
            const u64 hp = *reinterpret_cast<const u64*>(&hsF[i * 2]);
            aZ[0] = ffma2(pack2(wz.x), hp, aZ[0]);
            aZ[1] = ffma2(pack2(wz.y), hp, aZ[1]);
            aZ[2] = ffma2(pack2(wz.z), hp, aZ[2]);
            aZ[3] = ffma2(pack2(wz.w), hp, aZ[3]);
        }
#pragma unroll
        for (int c = 0; c < 4; c++)
            aZ[c] = fadd2(aZ[c],
                __shfl_xor_sync(0xffffffffu, aZ[c], 16));
        if (!(sl & 1)) {
            const int p = sl >> 1;
            float2 c0 = u2f(aZ[0]), c1 = u2f(aZ[1]);
            float2 c2 = u2f(aZ[2]), c3 = u2f(aZ[3]);
            *reinterpret_cast<float4*>(&part[((p*5+4)*2 + 0) * 64 + j0]) =
                make_float4(c0.x, c1.x, c2.x, c3.x);
            *reinterpret_cast<float4*>(&part[((p*5+4)*2 + 1) * 64 + j0]) =
                make_float4(c0.y, c1.y, c2.y, c3.y);
        }
        mbar_wait(rs_bar, t & 1);

        // ---- phase 2: h_tilde preact = rs @ Uh ----
        u64 a2[4];
#pragma unroll
        for (int c = 0; c < 4; c++) a2[c] = 0ull;
#pragma unroll
        for (int rr = 0; rr < 16; rr++) {
            const int i = (sl << 4) + rr;
            const float4 wh = *reinterpret_cast<const float4*>(&Ws[16384 + (i << 6) + j0]);
            const u64 rp = *reinterpret_cast<const u64*>(&rs[i * 2]);
            a2[0] = ffma2(pack2(wh.x), rp, a2[0]);
            a2[1] = ffma2(pack2(wh.y), rp, a2[1]);
            a2[2] = ffma2(pack2(wh.z), rp, a2[2]);
            a2[3] = ffma2(pack2(wh.w), rp, a2[3]);
        }
#pragma unroll
        for (int c = 0; c < 4; c++)
            a2[c] = fadd2(a2[c],
                __shfl_xor_sync(0xffffffffu, a2[c], 16));
        if (!(sl & 1)) {
            const int p = sl >> 1;       // reuse gate-0 slots of part
            float2 a0 = u2f(a2[0]), a1 = u2f(a2[1]);
            float2 b2 = u2f(a2[2]), b3 = u2f(a2[3]);
            *reinterpret_cast<float4*>(&part[((p*5)*2 + 0) * 64 + j0]) =
                make_float4(a0.x, a1.x, b2.x, b3.x);
            *reinterpret_cast<float4*>(&part[((p*5)*2 + 1) * 64 + j0]) =
                make_float4(a0.y, a1.y, b2.y, b3.y);
        }
        __syncthreads();

        // ---- final: z, h, mask, outputs, push new state ----
        if (tid < 128) {
            const int col = col0 + jg;
            float ph = 0.f, pz = 0.f;
#pragma unroll
            for (int p = 0; p < 8; p++) {
                ph += part[((p*5+0)*2 + ch) * 64 + jg];
                pz += part[((p*5+4)*2 + ch) * 64 + jg];
            }
            const float z  = sigmoidf_(xwz + pz);
            const float ht = 2.f * sigmoidf_(2.f * (xwh + ph)) - 1.f;  // tanh
            const float h  = z * hsumc * 0.25f + (1.f - z) * ht;
            const float ov = mreg ? h : 0.f;
            out[((size_t)bbg * Tn + t) * Un + col] = ov;
            const float st = mreg ? h : prevc;
            const uint32_t da = smem_u32(&sv[(0 * 256 + col) * 2 + ch]);
#pragma unroll
            for (int r4 = 0; r4 < 4; r4++) st_async_f32(da, st_bar, r4, st);
            if (t == Tn - 1) {
                out[(size_t)Bn * Tn * Un + (size_t)bbg * Un + col] = ov;
                out[(size_t)Bn * Tn * Un + (size_t)Bn * Un + (size_t)bbg * Un + col] = st;
            }
        }

        // ---- rotate pipeline registers ----
#pragma unroll
        for (int k = 0; k < 3; k++) { pf[k] = pfN[k]; def[k] = defN[k]; }
        xwr = nxr; xwz = nxz; xwh = nxh; mreg = nm;
    }

    // ---- exit drain: all inbound st.async must land before any CTA exits ----
    mbar_wait(st_bar, (Tn - 1) & 1);
    cluster_sync_();
}

// ---------------------------------------------------------------------------
// Inputs: 0 inputs, 1 dependencies, 2 mask, 3 initial_states,
// 4 Wz, 5 Wr, 6 Wh, 7 Uz, 8 Ur, 9 Uh, 10 bz, 11 br, 12 bh
// ---------------------------------------------------------------------------
extern "C" void kernel_launch(void* const* d_in, const int* in_sizes, int n_in,
                              void* d_out, int out_size) {
    const float* X    = (const float*)d_in[0];
    const int*   deps = (const int*)  d_in[1];
    const int*   mask = (const int*)  d_in[2];
    const float* init = (const float*)d_in[3];
    const float* Wz   = (const float*)d_in[4];
    const float* Wr   = (const float*)d_in[5];
    const float* Wh   = (const float*)d_in[6];
    const float* Uz   = (const float*)d_in[7];
    const float* Ur   = (const float*)d_in[8];
    const float* Uh   = (const float*)d_in[9];
    const float* bz   = (const float*)d_in[10];
    const float* br   = (const float*)d_in[11];
    const float* bh   = (const float*)d_in[12];
    float* out = (float*)d_out;

    cudaFuncSetAttribute(rnn_seq4, cudaFuncAttributeMaxDynamicSharedMemorySize,
                         SMEM_BYTES);

    dim3 g1(256, 6);   // (32768/128, 768/128)
    xw_gemm<<<g1, 256>>>(X, Wr, Wz, Wh, br, bz, bh);
    rnn_seq4<<<128, 256, SMEM_BYTES>>>(deps, mask, init, Uz, Ur, Uh, out);
}

// round 17
// speedup vs baseline: 1.1262x; 1.0368x over previous
#include <cuda_runtime.h>
#include <math.h>
#include <stdint.h>

#define Bn 64
#define Tn 512
#define Dn 256
#define Un 256
#define NCOL 64            // output columns owned by each CTA (Un / cluster4)

// (b*T + t, [r|z|h], u) : x@W + bias, precomputed
__device__ float g_xw[(size_t)Bn * Tn * 3 * Un];
// (cluster, t, u, ch) : masked state buffer, 2 chains packed
__device__ float g_buf[(size_t)(Bn / 2) * Tn * Un * 2];

__device__ __forceinline__ float sigmoidf_(float x) {
    return 1.f / (1.f + __expf(-x));
}
__device__ __forceinline__ uint32_t smem_u32(const void* p) {
    return (uint32_t)__cvta_generic_to_shared(p);
}
__device__ __forceinline__ void cluster_sync_() {
    asm volatile("barrier.cluster.arrive.aligned;" ::: "memory");
    asm volatile("barrier.cluster.wait.aligned;"   ::: "memory");
}
__device__ __forceinline__ void mbar_init(uint32_t bar, uint32_t cnt) {
    asm volatile("mbarrier.init.shared.b64 [%0], %1;" :: "r"(bar), "r"(cnt) : "memory");
}
__device__ __forceinline__ void mbar_expect_tx(uint32_t bar, uint32_t bytes) {
    asm volatile("mbarrier.arrive.expect_tx.shared.b64 _, [%0], %1;"
                 :: "r"(bar), "r"(bytes) : "memory");
}
__device__ __forceinline__ void mbar_wait(uint32_t bar, uint32_t parity) {
    asm volatile(
        "{\n\t.reg .pred P;\n\t"
        "W_%=:\n\t"
        "mbarrier.try_wait.parity.acquire.cta.shared::cta.b64 P, [%0], %1, 0x989680;\n\t"
        "@!P bra W_%=;\n\t"
        "}" :: "r"(bar), "r"(parity) : "memory");
}
// async store of one f32 to cluster CTA `rank`'s smem, completing on its mbarrier
__device__ __forceinline__ void st_async_f32(uint32_t daddr, uint32_t baddr,
                                             int rank, float v) {
    uint32_t ra, rb;
    asm("mapa.shared::cluster.u32 %0, %1, %2;" : "=r"(ra) : "r"(daddr), "r"(rank));
    asm("mapa.shared::cluster.u32 %0, %1, %2;" : "=r"(rb) : "r"(baddr), "r"(rank));
    asm volatile(
        "st.async.shared::cluster.mbarrier::complete_tx::bytes.b32 [%0], %1, [%2];"
        :: "r"(ra), "r"(__float_as_uint(v)), "r"(rb) : "memory");
}

// ---- packed f32x2 helpers ----
typedef unsigned long long u64;
__device__ __forceinline__ u64 pack2(float a) {
    u64 r; asm("mov.b64 %0, {%1, %1};" : "=l"(r) : "f"(a)); return r;
}
__device__ __forceinline__ u64 ffma2(u64 a, u64 b, u64 c) {
    u64 d; asm("fma.rn.f32x2 %0, %1, %2, %3;" : "=l"(d) : "l"(a), "l"(b), "l"(c));
    return d;
}
__device__ __forceinline__ u64 fadd2(u64 a, u64 b) {
    u64 d; asm("add.rn.f32x2 %0, %1, %2;" : "=l"(d) : "l"(a), "l"(b));
    return d;
}
__device__ __forceinline__ float2 u2f(u64 v) {
    float2 r; asm("mov.b64 {%0, %1}, %2;" : "=f"(r.x), "=f"(r.y) : "l"(v));
    return r;
}

// ---------------------------------------------------------------------------
// Kernel 1: P = X @ [Wr | Wz | Wh] + biases. f32x2 microkernel,
// double-buffered, float As (R14 configuration — measured best).
// ---------------------------------------------------------------------------
__global__ __launch_bounds__(256) void xw_gemm(
    const float* __restrict__ X,
    const float* __restrict__ Wr, const float* __restrict__ Wz,
    const float* __restrict__ Wh,
    const float* __restrict__ br, const float* __restrict__ bz,
    const float* __restrict__ bh)
{
    __shared__ float As[2][8][128];
    __shared__ float Bs[2][8][128];
    const int tid = threadIdx.x;
    const int m0 = blockIdx.x * 128;
    const int n0 = blockIdx.y * 128;
    const int gi = n0 >> 8;
    const int u0 = n0 & 255;
    const float* __restrict__ W  = (gi == 0) ? Wr : (gi == 1 ? Wz : Wh);
    const float* __restrict__ bb = (gi == 0) ? br : (gi == 1 ? bz : bh);

    const int arow = tid >> 1;
    const int acol = (tid & 1) * 4;
    const int brow = tid >> 5;
    const int bcol = (tid & 31) * 4;
    const int ty = tid >> 4, tx = tid & 15;

    u64 acc[8][4];
#pragma unroll
    for (int i = 0; i < 8; i++)
#pragma unroll
        for (int j = 0; j < 4; j++) acc[i][j] = 0ull;

    // preload tile k0 = 0
    {
        float4 a4 = *reinterpret_cast<const float4*>(
            &X[(size_t)(m0 + arow) * Dn + acol]);
        float4 b4 = *reinterpret_cast<const float4*>(
            &W[(size_t)brow * Un + u0 + bcol]);
        As[0][acol + 0][arow] = a4.x;
        As[0][acol + 1][arow] = a4.y;
        As[0][acol + 2][arow] = a4.z;
        As[0][acol + 3][arow] = a4.w;
        *reinterpret_cast<float4*>(&Bs[0][brow][bcol]) = b4;
    }
    __syncthreads();

    int buf = 0;
    for (int k0 = 0; k0 < Dn; k0 += 8) {
        const bool more = (k0 + 8 < Dn);
        float4 a4n, b4n;
        if (more) {
            a4n = *reinterpret_cast<const float4*>(
                &X[(size_t)(m0 + arow) * Dn + k0 + 8 + acol]);
            b4n = *reinterpret_cast<const float4*>(
                &W[(size_t)(k0 + 8 + brow) * Un + u0 + bcol]);
        }
#pragma unroll
        for (int k = 0; k < 8; k++) {
            float4 a0 = *reinterpret_cast<const float4*>(&As[buf][k][ty * 8]);
            float4 a1 = *reinterpret_cast<const float4*>(&As[buf][k][ty * 8 + 4]);
            const u64* bp = reinterpret_cast<const u64*>(&Bs[buf][k][tx * 8]);
            const u64 b0 = bp[0], b1 = bp[1], b2 = bp[2], b3 = bp[3];
            const float av[8] = {a0.x, a0.y, a0.z, a0.w, a1.x, a1.y, a1.z, a1.w};
#pragma unroll
            for (int i = 0; i < 8; i++) {
                const u64 pa = pack2(av[i]);
                acc[i][0] = ffma2(pa, b0, acc[i][0]);
                acc[i][1] = ffma2(pa, b1, acc[i][1]);
                acc[i][2] = ffma2(pa, b2, acc[i][2]);
                acc[i][3] = ffma2(pa, b3, acc[i][3]);
            }
        }
        if (more) {
            As[buf ^ 1][acol + 0][arow] = a4n.x;
            As[buf ^ 1][acol + 1][arow] = a4n.y;
            As[buf ^ 1][acol + 2][arow] = a4n.z;
            As[buf ^ 1][acol + 3][arow] = a4n.w;
            *reinterpret_cast<float4*>(&Bs[buf ^ 1][brow][bcol]) = b4n;
        }
        __syncthreads();
        buf ^= 1;
    }
    const u64* bbp = reinterpret_cast<const u64*>(&bb[u0 + tx * 8]);
    const u64 bias2[4] = {bbp[0], bbp[1], bbp[2], bbp[3]};
#pragma unroll
    for (int i = 0; i < 8; i++) {
        u64* orow = reinterpret_cast<u64*>(
            g_xw + (size_t)(m0 + ty * 8 + i) * 768 + n0 + tx * 8);
#pragma unroll
        for (int j = 0; j < 4; j++)
            orow[j] = fadd2(acc[i][j], bias2[j]);
    }
}

// ---------------------------------------------------------------------------
// Kernel 2: recurrence — exact R14 structure (measured best: 1685.6 us).
// Ur in registers (read twice per step: phase1a + phase1b), Uz/Uh in SMEM,
// column-partitioned phase 2 with rs broadcast, s0-pipelined step,
// mbarrier/st.async exchange, exit drain + cluster_sync.
//
// smem (floats):
//   W    [2][256][64]     @0       131072 B  (Uz @0, Uh @16384)
//   part [8][5][2][64]    @32768    20480 B  (g0..3 = r; g4 = z; g0 reused h)
//   sv   [4][256][2]      @37888     8192 B
//   hs3  [256][2]         @39936     2048 B
//   hsF  [256][2]         @40448     2048 B
//   rs   [256][2]         @40960     2048 B
//   bars (2 x u64)        @41472       16 B
// ---------------------------------------------------------------------------
#define OFF_PART 32768
#define OFF_S    37888
#define OFF_HS   39936
#define OFF_HSF  40448
#define OFF_RS   40960
#define OFF_BAR  41472
#define SMEM_BYTES (41476 * 4)

__global__ __launch_bounds__(256, 1) __cluster_dims__(4, 1, 1)
void rnn_seq4(const int*   __restrict__ deps,    // (T, 3)
              const int*   __restrict__ mask,    // (B, T)
              const float* __restrict__ init,    // (4, B, U)
              const float* __restrict__ Uzm, const float* __restrict__ Urm,
              const float* __restrict__ Uhm,
              float*       __restrict__ out)
{
    extern __shared__ float sm[];
    float* Ws   = sm;
    float* part = sm + OFF_PART;
    float* sv   = sm + OFF_S;
    float* hs3  = sm + OFF_HS;
    float* hsF  = sm + OFF_HSF;
    float* rs   = sm + OFF_RS;

    const int tid  = threadIdx.x;
    const int rank = blockIdx.x & 3;
    const int cl   = blockIdx.x >> 2;
    const int b0   = cl * 2, b1 = b0 + 1;
    const int col0 = rank * NCOL;

    const uint32_t rs_bar = smem_u32(sm + OFF_BAR);
    const uint32_t st_bar = rs_bar + 8;

    const int sl = tid >> 4;          // i-slice 0..15
    const int j0 = (tid & 15) * 4;    // 4 local columns

    // ---- Uz/Uh into smem; Ur into registers (thread-private slice) ----
    for (int idx = tid; idx < 256 * NCOL; idx += 256) {
        int i = idx >> 6, j = idx & 63;
        Ws[idx]          = Uzm[i * Un + col0 + j];
        Ws[16384 + idx]  = Uhm[i * Un + col0 + j];
    }
    float4 wr4[16];
#pragma unroll
    for (int rr = 0; rr < 16; rr++)
        wr4[rr] = *reinterpret_cast<const float4*>(
            &Urm[((sl << 4) + rr) * Un + col0 + j0]);
    if (tid == 0) { mbar_init(rs_bar, 1); mbar_init(st_bar, 1); }

    // ---- preload initial states (t=0) ----
#pragma unroll
    for (int k = 0; k < 4; k++) {
        sv[(k * 256 + tid) * 2 + 0] = init[((size_t)k * Bn + b0) * Un + tid];
        sv[(k * 256 + tid) * 2 + 1] = init[((size_t)k * Bn + b1) * Un + tid];
    }
    // ---- preload xw/mask for t=0 (gate threads only) ----
    float xwr = 0.f, xwz = 0.f, xwh = 0.f;
    int   mreg = 0;
    const int ch = tid >> 6, jg = tid & 63;        // valid for tid<128
    const int bbg = ch ? b1 : b0;
    if (tid < 128) {
        const float* base = g_xw + ((size_t)bbg * Tn + 0) * 768;
        xwr = base[col0 + jg];
        xwz = base[256 + col0 + jg];
        xwh = base[512 + col0 + jg];
        mreg = mask[bbg * Tn + 0];
    }
    asm volatile("fence.proxy.async.shared::cta;" ::: "memory");
    __syncthreads();
    cluster_sync_();          // bars visible cluster-wide before any st.async

    u64  pf[3]  = {0ull, 0ull, 0ull};
    bool def[3] = {false, false, false};

    for (int t = 0; t < Tn; t++) {
        if (tid == 0) mbar_expect_tx(rs_bar, 2048);

        // ---- top: sv[1..3] update + hs3 from registers ----
        u64 p0, p1, p2;
        if (t == 0) {
            p0 = *reinterpret_cast<const u64*>(&sv[(1*256 + tid) * 2]);
            p1 = *reinterpret_cast<const u64*>(&sv[(2*256 + tid) * 2]);
            p2 = *reinterpret_cast<const u64*>(&sv[(3*256 + tid) * 2]);
        } else {
            p0 = def[0] ? 0ull : pf[0];
            p1 = def[1] ? 0ull : pf[1];
            p2 = def[2] ? 0ull : pf[2];
            *reinterpret_cast<u64*>(&sv[(1*256 + tid) * 2]) = p0;
            *reinterpret_cast<u64*>(&sv[(2*256 + tid) * 2]) = p1;
            *reinterpret_cast<u64*>(&sv[(3*256 + tid) * 2]) = p2;
        }
        *reinterpret_cast<u64*>(&hs3[tid * 2]) = fadd2(fadd2(p0, p1), p2);
        const int cnt = (int)def[0] + (int)def[1] + (int)def[2];
        const float cnt1f = 1.f + (float)cnt;
        __syncthreads();

        // ---- xw/mask prefetch for t+1 (pre-wait zone) ----
        float nxr = 0.f, nxz = 0.f, nxh = 0.f;
        int nm = 0;
        if (tid < 128) {
            const int tn = (t + 1 < Tn) ? t + 1 : t;
            const float* base = g_xw + ((size_t)bbg * Tn + tn) * 768;
            nxr = base[col0 + jg];
            nxz = base[256 + col0 + jg];
            nxh = base[512 + col0 + jg];
            nm  = mask[bbg * Tn + tn];
        }

        // ---- phase 1a: r preacts for states 1..3 (pre-wait, regs Ur) ----
        u64 aR[4][4];
#pragma unroll
        for (int k = 0; k < 4; k++)
#pragma unroll
            for (int c = 0; c < 4; c++) aR[k][c] = 0ull;
#pragma unroll
        for (int rr = 0; rr < 16; rr++) {
            const int i = (sl << 4) + rr;
            const u64 s1 = *reinterpret_cast<const u64*>(&sv[(1*256 + i) * 2]);
            const u64 s2 = *reinterpret_cast<const u64*>(&sv[(2*256 + i) * 2]);
            const u64 s3 = *reinterpret_cast<const u64*>(&sv[(3*256 + i) * 2]);
            const u64 w0 = pack2(wr4[rr].x), w1 = pack2(wr4[rr].y),
                      w2 = pack2(wr4[rr].z), w3 = pack2(wr4[rr].w);
            aR[1][0] = ffma2(w0, s1, aR[1][0]);
            aR[1][1] = ffma2(w1, s1, aR[1][1]);
            aR[1][2] = ffma2(w2, s1, aR[1][2]);
            aR[1][3] = ffma2(w3, s1, aR[1][3]);
            aR[2][0] = ffma2(w0, s2, aR[2][0]);
            aR[2][1] = ffma2(w1, s2, aR[2][1]);
            aR[2][2] = ffma2(w2, s2, aR[2][2]);
            aR[2][3] = ffma2(w3, s2, aR[2][3]);
            aR[3][0] = ffma2(w0, s3, aR[3][0]);
            aR[3][1] = ffma2(w1, s3, aR[3][1]);
            aR[3][2] = ffma2(w2, s3, aR[3][2]);
            aR[3][3] = ffma2(w3, s3, aR[3][3]);
        }

        // ---- wait for s0 = st(t-1); then set st expectation for this step ----
        if (t > 0) mbar_wait(st_bar, (t - 1) & 1);
        if (tid == 0) mbar_expect_tx(st_bar, 2048);

        // ---- g_buf row t-1 + data prefetch for t+1 ----
        const u64 s0mine = *reinterpret_cast<const u64*>(&sv[tid * 2]);
        if (t > 0)
            *reinterpret_cast<u64*>(
                &g_buf[(((size_t)cl * Tn + (t - 1)) * Un + tid) * 2]) = s0mine;
        u64  pfN[3];
        bool defN[3];
#pragma unroll
        for (int k = 0; k < 3; k++) {
            const int d = deps[t * 3 + k];
            defN[k] = (d >= t);      // d == t: gathered state is st(t) = next s0
            pfN[k] = 0ull;
            if (d < t)
                pfN[k] = *reinterpret_cast<const u64*>(
                    &g_buf[(((size_t)cl * Tn + d) * Un + tid) * 2]);
        }

        // ---- phase 1b: s0 dot (regs Ur) + hsF snapshot ----
        const u64 cf = pack2(cnt1f);
        u64 cc[4] = {0ull, 0ull, 0ull, 0ull};
#pragma unroll
        for (int rr = 0; rr < 16; rr++) {
            const int i = (sl << 4) + rr;
            const u64 s0 = *reinterpret_cast<const u64*>(&sv[(0*256 + i) * 2]);
            const u64 h3 = *reinterpret_cast<const u64*>(&hs3[i * 2]);
            *reinterpret_cast<u64*>(&hsF[i * 2]) = ffma2(cf, s0, h3);
            cc[0] = ffma2(pack2(wr4[rr].x), s0, cc[0]);
            cc[1] = ffma2(pack2(wr4[rr].y), s0, cc[1]);
            cc[2] = ffma2(pack2(wr4[rr].z), s0, cc[2]);
            cc[3] = ffma2(pack2(wr4[rr].w), s0, cc[3]);
        }
#pragma unroll
        for (int c = 0; c < 4; c++) {
            aR[0][c] = fadd2(aR[0][c], cc[c]);
            if (def[0]) aR[1][c] = fadd2(aR[1][c], cc[c]);
            if (def[1]) aR[2][c] = fadd2(aR[2][c], cc[c]);
            if (def[2]) aR[3][c] = fadd2(aR[3][c], cc[c]);
        }
#pragma unroll
        for (int k = 0; k < 4; k++)
#pragma unroll
            for (int c = 0; c < 4; c++)
                aR[k][c] = fadd2(aR[k][c],
                    __shfl_xor_sync(0xffffffffu, aR[k][c], 16));
        if (!(sl & 1)) {
            const int p = sl >> 1;
#pragma unroll
            for (int g = 0; g < 4; g++) {
                float2 a0 = u2f(aR[g][0]), a1 = u2f(aR[g][1]);
                float2 a2 = u2f(aR[g][2]), a3 = u2f(aR[g][3]);
                *reinterpret_cast<float4*>(&part[((p*5+g)*2 + 0) * 64 + j0]) =
                    make_float4(a0.x, a1.x, a2.x, a3.x);
                *reinterpret_cast<float4*>(&part[((p*5+g)*2 + 1) * 64 + j0]) =
                    make_float4(a0.y, a1.y, a2.y, a3.y);
            }
        }
        __syncthreads();

        // ---- gate stage (tid<128): r gates, rsum; snapshots; push rs ----
        float hsumc = 0.f, prevc = 0.f;
        if (tid < 128) {
            float pr[4] = {0.f, 0.f, 0.f, 0.f};
#pragma unroll
            for (int p = 0; p < 8; p++)
#pragma unroll
                for (int g = 0; g < 4; g++)
                    pr[g] += part[((p*5+g)*2 + ch) * 64 + jg];
            const int col = col0 + jg;
            const float s0c = sv[(0*256 + col) * 2 + ch];
            const float s1v = sv[(1*256 + col) * 2 + ch];   // 0 if deferred
            const float s2v = sv[(2*256 + col) * 2 + ch];
            const float s3v = sv[(3*256 + col) * 2 + ch];
            const float s1g = def[0] ? s0c : s1v;
            const float s2g = def[1] ? s0c : s2v;
            const float s3g = def[2] ? s0c : s3v;
            hsumc = s0c * cnt1f + s1v + s2v + s3v;
            prevc = (t == 0) ? 0.f : s0c;
            const float rsum = sigmoidf_(xwr + pr[0]) * s0c
                             + sigmoidf_(xwr + pr[1]) * s1g
                             + sigmoidf_(xwr + pr[2]) * s2g
                             + sigmoidf_(xwr + pr[3]) * s3g;
            const uint32_t da = smem_u32(&rs[col * 2 + ch]);
#pragma unroll
            for (int r4 = 0; r4 < 4; r4++) st_async_f32(da, rs_bar, r4, rsum);
        }

        // ---- Z matvec (all threads; Uz in smem, hsF in smem) ----
        u64 aZ[4];
#pragma unroll
        for (int c = 0; c < 4; c++) aZ[c] = 0ull;
#pragma unroll
        for (int rr = 0; rr < 16; rr++) {
            const int i = (sl << 4) + rr;
            const float4 wz = *reinterpret_cast<const float4*>(&Ws[(i << 6) + j0]);
            const u64 hp = *reinterpret_cast<const u64*>(&hsF[i * 2]);
            aZ[0] = ffma2(pack2(wz.x), hp, aZ[0]);
            aZ[1] = ffma2(pack2(wz.y), hp, aZ[1]);
            aZ[2] = ffma2(pack2(wz.z), hp, aZ[2]);
            aZ[3] = ffma2(pack2(wz.w), hp, aZ[3]);
        }
#pragma unroll
        for (int c = 0; c < 4; c++)
            aZ[c] = fadd2(aZ[c],
                __shfl_xor_sync(0xffffffffu, aZ[c], 16));
        if (!(sl & 1)) {
            const int p = sl >> 1;
            float2 c0 = u2f(aZ[0]), c1 = u2f(aZ[1]);
            float2 c2 = u2f(aZ[2]), c3 = u2f(aZ[3]);
            *reinterpret_cast<float4*>(&part[((p*5+4)*2 + 0) * 64 + j0]) =
                make_float4(c0.x, c1.x, c2.x, c3.x);
            *reinterpret_cast<float4*>(&part[((p*5+4)*2 + 1) * 64 + j0]) =
                make_float4(c0.y, c1.y, c2.y, c3.y);
        }
        mbar_wait(rs_bar, t & 1);

        // ---- phase 2: h_tilde preact = rs @ Uh ----
        u64 a2[4];
#pragma unroll
        for (int c = 0; c < 4; c++) a2[c] = 0ull;
#pragma unroll
        for (int rr = 0; rr < 16; rr++) {
            const int i = (sl << 4) + rr;
            const float4 wh = *reinterpret_cast<const float4*>(&Ws[16384 + (i << 6) + j0]);
            const u64 rp = *reinterpret_cast<const u64*>(&rs[i * 2]);
            a2[0] = ffma2(pack2(wh.x), rp, a2[0]);
            a2[1] = ffma2(pack2(wh.y), rp, a2[1]);
            a2[2] = ffma2(pack2(wh.z), rp, a2[2]);
            a2[3] = ffma2(pack2(wh.w), rp, a2[3]);
        }
#pragma unroll
        for (int c = 0; c < 4; c++)
            a2[c] = fadd2(a2[c],
                __shfl_xor_sync(0xffffffffu, a2[c], 16));
        if (!(sl & 1)) {
            const int p = sl >> 1;       // reuse gate-0 slots of part
            float2 a0 = u2f(a2[0]), a1 = u2f(a2[1]);
            float2 b2 = u2f(a2[2]), b3 = u2f(a2[3]);
            *reinterpret_cast<float4*>(&part[((p*5)*2 + 0) * 64 + j0]) =
                make_float4(a0.x, a1.x, b2.x, b3.x);
            *reinterpret_cast<float4*>(&part[((p*5)*2 + 1) * 64 + j0]) =
                make_float4(a0.y, a1.y, b2.y, b3.y);
        }
        __syncthreads();

        // ---- final: z, h, mask, outputs, push new state ----
        if (tid < 128) {
            const int col = col0 + jg;
            float ph = 0.f, pz = 0.f;
#pragma unroll
            for (int p = 0; p < 8; p++) {
                ph += part[((p*5+0)*2 + ch) * 64 + jg];
                pz += part[((p*5+4)*2 + ch) * 64 + jg];
            }
            const float z  = sigmoidf_(xwz + pz);
            const float ht = 2.f * sigmoidf_(2.f * (xwh + ph)) - 1.f;  // tanh
            const float h  = z * hsumc * 0.25f + (1.f - z) * ht;
            const float ov = mreg ? h : 0.f;
            out[((size_t)bbg * Tn + t) * Un + col] = ov;
            const float st = mreg ? h : prevc;
            const uint32_t da = smem_u32(&sv[(0 * 256 + col) * 2 + ch]);
#pragma unroll
            for (int r4 = 0; r4 < 4; r4++) st_async_f32(da, st_bar, r4, st);
            if (t == Tn - 1) {
                out[(size_t)Bn * Tn * Un + (size_t)bbg * Un + col] = ov;
                out[(size_t)Bn * Tn * Un + (size_t)Bn * Un + (size_t)bbg * Un + col] = st;
            }
        }

        // ---- rotate pipeline registers ----
#pragma unroll
        for (int k = 0; k < 3; k++) { pf[k] = pfN[k]; def[k] = defN[k]; }
        xwr = nxr; xwz = nxz; xwh = nxh; mreg = nm;
    }

    // ---- exit drain: all inbound st.async must land before any CTA exits ----
    mbar_wait(st_bar, (Tn - 1) & 1);
    cluster_sync_();
}

// ---------------------------------------------------------------------------
// Inputs: 0 inputs, 1 dependencies, 2 mask, 3 initial_states,
// 4 Wz, 5 Wr, 6 Wh, 7 Uz, 8 Ur, 9 Uh, 10 bz, 11 br, 12 bh
// ---------------------------------------------------------------------------
extern "C" void kernel_launch(void* const* d_in, const int* in_sizes, int n_in,
                              void* d_out, int out_size) {
    const float* X    = (const float*)d_in[0];
    const int*   deps = (const int*)  d_in[1];
    const int*   mask = (const int*)  d_in[2];
    const float* init = (const float*)d_in[3];
    const float* Wz   = (const float*)d_in[4];
    const float* Wr   = (const float*)d_in[5];
    const float* Wh   = (const float*)d_in[6];
    const float* Uz   = (const float*)d_in[7];
    const float* Ur   = (const float*)d_in[8];
    const float* Uh   = (const float*)d_in[9];
    const float* bz   = (const float*)d_in[10];
    const float* br   = (const float*)d_in[11];
    const float* bh   = (const float*)d_in[12];
    float* out = (float*)d_out;

    cudaFuncSetAttribute(rnn_seq4, cudaFuncAttributeMaxDynamicSharedMemorySize,
                         SMEM_BYTES);

    dim3 g1(256, 6);   // (32768/128, 768/128)
    xw_gemm<<<g1, 256>>>(X, Wr, Wz, Wh, br, bz, bh);
    rnn_seq4<<<128, 256, SMEM_BYTES>>>(deps, mask, init, Uz, Ur, Uh, out);
}